// round 7
// baseline (speedup 1.0000x reference)
#include <cuda_runtime.h>
#include <math.h>

#define BATCH 64
#define HW 224
#define IMG_PIX (HW * HW)   // 50176
#define NPIX (BATCH * IMG_PIX)
#define SMEM_IMG_BYTES (IMG_PIX * 4)   // 200704 B dynamic smem per CTA

// Scratch: channel-planar copy of the input + the 5x5x3 metric grid per image.
__device__ float g_planar[3ULL * NPIX];      // [ch][b][r][c]
__device__ float g_grid[BATCH * 5 * 5 * 3];  // [b][metric][kidx][ch]

// ---------------------------------------------------------------------------
// Pass 1: NHWC -> planar, float4-vectorized (4 pixels / thread)
// ---------------------------------------------------------------------------
__global__ void transpose_kernel(const float* __restrict__ in) {
    int g = blockIdx.x * blockDim.x + threadIdx.x;   // group of 4 pixels
    if (g >= NPIX / 4) return;
    const float4* p = (const float4*)(in + (size_t)g * 12);
    float4 A = __ldg(&p[0]);   // p0.r p0.g p0.b p1.r
    float4 B = __ldg(&p[1]);   // p1.g p1.b p2.r p2.g
    float4 C = __ldg(&p[2]);   // p2.b p3.r p3.g p3.b
    float4 rch = make_float4(A.x, A.w, B.z, C.y);
    float4 gch = make_float4(A.y, B.x, B.w, C.z);
    float4 bch = make_float4(A.z, B.y, C.x, C.w);
    ((float4*)(g_planar + 0ULL * NPIX))[g] = rch;
    ((float4*)(g_planar + 1ULL * NPIX))[g] = gch;
    ((float4*)(g_planar + 2ULL * NPIX))[g] = bch;
}

// ---------------------------------------------------------------------------
// Pass 2: per-(b, ch, k) block. Whole channel image staged in shared memory
// (coalesced float4 loads), patch reads via conflict-free LDS (odd stride).
// ---------------------------------------------------------------------------
extern __shared__ float s_img[];   // IMG_PIX floats

template <int K>
__device__ __forceinline__ void compute_block(int b, int ch, int kidx) {
    constexpr int ROWS = (HW + K - 1) / K;
    constexpr int P = ROWS * ROWS;
    constexpr int PAD = (ROWS * K - HW) / 2;   // top/left pad (== ph // 2)
    constexpr int KK = K * K;
    constexpr unsigned MASK = (1u << K) - 1u;

    __shared__ int s_hist[KK + 1];
    __shared__ int s_ncomp, s_perc, s_marea;

    for (int i = threadIdx.x; i < KK + 1; i += blockDim.x) s_hist[i] = 0;
    if (threadIdx.x == 0) { s_ncomp = 0; s_perc = 0; s_marea = 0; }

    // ---- stage the whole channel image into shared memory ----
    {
        const float4* src = (const float4*)(g_planar + ((size_t)ch * BATCH + b) * IMG_PIX);
        float4* dst = (float4*)s_img;
        for (int i = threadIdx.x; i < IMG_PIX / 4; i += blockDim.x)
            dst[i] = __ldg(&src[i]);
    }
    __syncthreads();

    const float thr = (float)K;
    int t_ncomp = 0, t_perc = 0, t_marea = 0;

    for (int p = threadIdx.x; p < P; p += blockDim.x) {
        int pr = p / ROWS, pc = p - pr * ROWS;
        int r0 = pr * K - PAD, c0 = pc * K - PAD;

        // center pixel is always in-bounds for these (K, 224) combos
        float cv = s_img[(r0 + K / 2) * HW + (c0 + K / 2)];

        // ---- binarize patch into K row bitmasks (LDS, odd stride => no conflicts) ----
        unsigned rows[K];
        int ones = 0;
        bool colfast = (c0 >= 0) && (c0 + K <= HW);
        #pragma unroll
        for (int rr = 0; rr < K; rr++) {
            int r = r0 + rr;
            unsigned m = 0;
            if (r >= 0 && r < HW) {
                if (colfast) {
                    const float* rp = s_img + r * HW + c0;
                    #pragma unroll
                    for (int cc = 0; cc < K; cc++) {
                        float v = rp[cc];
                        m |= (fabsf(v - cv) <= thr) ? (1u << cc) : 0u;
                    }
                } else {
                    #pragma unroll
                    for (int cc = 0; cc < K; cc++) {
                        int c = c0 + cc;
                        float v = (c >= 0 && c < HW) ? s_img[r * HW + c] : 0.0f;
                        m |= (fabsf(v - cv) <= thr) ? (1u << cc) : 0u;
                    }
                }
            } else {
                m = (cv <= thr) ? MASK : 0u;   // fully-padded row (values 0)
            }
            rows[rr] = m;
            ones += __popc(m);
        }

        // ---- bulk strip of singletons and isolated dominoes (branch-free) ----
        unsigned rem[K];
        int n_iso = 0, n_dom = 0;
        unsigned e1p = 0;
        #pragma unroll
        for (int i = 0; i < K; i++) {
            unsigned l = (rows[i] << 1) & MASK;
            unsigned r = rows[i] >> 1;
            unsigned u = (i > 0) ? rows[i - 1] : 0u;
            unsigned d = (i < K - 1) ? rows[i + 1] : 0u;
            unsigned s  = l ^ r, ca = l & r;
            unsigned t2 = u ^ d, cb = u & d;
            unsigned low = s ^ t2;
            unsigned ge2 = ca | cb | (s & t2);
            unsigned any = low | ge2;
            unsigned e1  = rows[i] & low & ~ge2;

            n_iso += __popc(rows[i] & ~any);
            unsigned rm = rows[i] & any;

            unsigned hd = e1 & (e1 >> 1);        // isolated horizontal dominoes
            n_dom += __popc(hd);
            rm &= ~(hd | ((hd << 1) & MASK));

            unsigned vd = e1p & e1;              // isolated vertical dominoes
            n_dom += __popc(vd);
            rm &= ~vd;
            if (i > 0) rem[i - 1] &= ~vd;

            rem[i] = rm;
            e1p = e1;
        }

        int remaining = ones - n_iso - 2 * n_dom;
        int ncomp = n_iso + n_dom;
        int maxc = (n_dom > 0) ? 2 : ((n_iso > 0) ? 1 : 0);

        // ---- flood-fill only the residual clustered cells ----
        while (remaining > 0) {
            unsigned comp[K];
            #pragma unroll
            for (int i = 0; i < K; i++) comp[i] = 0;
            int seeded = 0;
            #pragma unroll
            for (int i = 0; i < K; i++) {
                if (!seeded && rem[i]) { comp[i] = rem[i] & (0u - rem[i]); seeded = 1; }
            }
            int changed = 1;
            while (changed) {
                changed = 0;
                #pragma unroll
                for (int i = 0; i < K; i++) {          // downward sweep
                    unsigned acc = comp[i] | (comp[i] << 1) | (comp[i] >> 1);
                    if (i > 0) acc |= comp[i - 1];
                    if (i < K - 1) acc |= comp[i + 1];
                    acc &= rem[i];
                    if (acc != comp[i]) { comp[i] = acc; changed = 1; }
                }
                #pragma unroll
                for (int i = K - 1; i >= 0; i--) {     // upward sweep
                    unsigned acc = comp[i] | (comp[i] << 1) | (comp[i] >> 1);
                    if (i > 0) acc |= comp[i - 1];
                    if (i < K - 1) acc |= comp[i + 1];
                    acc &= rem[i];
                    if (acc != comp[i]) { comp[i] = acc; changed = 1; }
                }
            }
            int sz = 0;
            #pragma unroll
            for (int i = 0; i < K; i++) { sz += __popc(comp[i]); rem[i] &= ~comp[i]; }
            remaining -= sz;
            ncomp++;
            if (sz > maxc) maxc = sz;
        }

        int zeros = KK - ones;
        int marea = (zeros > maxc) ? zeros : maxc;   // label-0 (bg) count vs max comp
        int perc = ((float)ones / (float)KK >= 0.59275f) ? 1 : 0;

        atomicAdd(&s_hist[ones], 1);
        t_ncomp += ncomp;
        t_perc += perc;
        t_marea += marea;
    }

    // warp-reduce the three scalar sums, then one shared atomic per warp
    #pragma unroll
    for (int off = 16; off > 0; off >>= 1) {
        t_ncomp += __shfl_down_sync(0xffffffffu, t_ncomp, off);
        t_perc  += __shfl_down_sync(0xffffffffu, t_perc, off);
        t_marea += __shfl_down_sync(0xffffffffu, t_marea, off);
    }
    if ((threadIdx.x & 31) == 0) {
        atomicAdd(&s_ncomp, t_ncomp);
        atomicAdd(&s_perc, t_perc);
        atomicAdd(&s_marea, t_marea);
    }
    __syncthreads();

    if (threadIdx.x == 0) {
        const float Pf = (float)P;
        float fd = 0.f, m = 0.f, m2 = 0.f;
        for (int j = 0; j < KK; j++) {            // bin KK intentionally dropped
            float pr = (float)s_hist[j] / Pf;
            float n = (float)(j + 1);
            fd += pr / n;
            m  += pr * n;
            m2 += pr * pr * n;
        }
        float lac = (m2 - m * m) / (m * m);
        float acn  = (float)(s_ncomp / P);        // tf integer reduce_mean
        float acp  = (float)(s_perc  / P);
        float acma = (float)(s_marea / P);

        float* g = g_grid + (size_t)b * 75;       // [metric][kidx][ch]
        g[(0 * 5 + kidx) * 3 + ch] = acn;
        g[(1 * 5 + kidx) * 3 + ch] = acp;
        g[(2 * 5 + kidx) * 3 + ch] = acma;
        g[(3 * 5 + kidx) * 3 + ch] = lac;
        g[(4 * 5 + kidx) * 3 + ch] = fd;
    }
}

__global__ __launch_bounds__(512, 1) void compute_kernel() {
    int bid = blockIdx.x;
    int kidx = bid / (BATCH * 3);
    int rest = bid - kidx * (BATCH * 3);
    int b = rest / 3, ch = rest - (rest / 3) * 3;
    switch (kidx) {
        case 0: compute_block<3>(b, ch, 0); break;
        case 1: compute_block<5>(b, ch, 1); break;
        case 2: compute_block<7>(b, ch, 2); break;
        case 3: compute_block<9>(b, ch, 3); break;
        case 4: compute_block<11>(b, ch, 4); break;
    }
}

// ---------------------------------------------------------------------------
// Pass 3: bilinear upsample 5x5x3 -> 224x224x3, float4-vectorized stores
// (half-pixel centers + edge clamp == jax.image.resize 'bilinear' upsampling)
// ---------------------------------------------------------------------------
__global__ void resize_kernel(float* __restrict__ out) {
    int g = blockIdx.x * blockDim.x + threadIdx.x;   // group of 4 pixels
    if (g >= NPIX / 4) return;
    int b = g / (IMG_PIX / 4);
    int within = g - b * (IMG_PIX / 4);
    int pix0 = within * 4;
    int i = pix0 / HW, j0 = pix0 - (pix0 / HW) * HW;  // 4 pixels share row i

    const float scale = 5.0f / 224.0f;
    float fy = ((float)i + 0.5f) * scale - 0.5f;
    float y0f = floorf(fy);
    float wy = fy - y0f;
    int y0 = min(4, max(0, (int)y0f));
    int y1 = min(4, max(0, (int)y0f + 1));

    const float* gr = g_grid + (size_t)b * 75;
    float vals[12];
    #pragma unroll
    for (int q = 0; q < 4; q++) {
        int j = j0 + q;
        float fx = ((float)j + 0.5f) * scale - 0.5f;
        float x0f = floorf(fx);
        float wx = fx - x0f;
        int x0 = min(4, max(0, (int)x0f));
        int x1 = min(4, max(0, (int)x0f + 1));
        #pragma unroll
        for (int c = 0; c < 3; c++) {
            float v00 = __ldg(&gr[(y0 * 5 + x0) * 3 + c]);
            float v01 = __ldg(&gr[(y0 * 5 + x1) * 3 + c]);
            float v10 = __ldg(&gr[(y1 * 5 + x0) * 3 + c]);
            float v11 = __ldg(&gr[(y1 * 5 + x1) * 3 + c]);
            float top = v00 * (1.0f - wx) + v01 * wx;
            float bot = v10 * (1.0f - wx) + v11 * wx;
            vals[q * 3 + c] = top * (1.0f - wy) + bot * wy;
        }
    }
    float4* o = (float4*)(out + (size_t)(b * IMG_PIX + pix0) * 3);
    o[0] = make_float4(vals[0], vals[1], vals[2],  vals[3]);
    o[1] = make_float4(vals[4], vals[5], vals[6],  vals[7]);
    o[2] = make_float4(vals[8], vals[9], vals[10], vals[11]);
}

// ---------------------------------------------------------------------------
extern "C" void kernel_launch(void* const* d_in, const int* in_sizes, int n_in,
                              void* d_out, int out_size) {
    const float* in = (const float*)d_in[0];
    float* out = (float*)d_out;

    cudaFuncSetAttribute(compute_kernel,
                         cudaFuncAttributeMaxDynamicSharedMemorySize,
                         SMEM_IMG_BYTES);

    transpose_kernel<<<(NPIX / 4 + 255) / 256, 256>>>(in);
    compute_kernel<<<5 * BATCH * 3, 512, SMEM_IMG_BYTES>>>();
    resize_kernel<<<(NPIX / 4 + 255) / 256, 256>>>(out);
}

// round 8
// speedup vs baseline: 1.6960x; 1.6960x over previous
#include <cuda_runtime.h>
#include <math.h>

#define BATCH 64
#define HW 224
#define IMG_PIX (HW * HW)   // 50176
#define NPIX (BATCH * IMG_PIX)

// Scratch: channel-planar copy of the input + the 5x5x3 metric grid per image.
__device__ float g_planar[3ULL * NPIX];      // [ch][b][r][c]
__device__ float g_grid[BATCH * 5 * 5 * 3];  // [b][metric][kidx][ch]

// ---------------------------------------------------------------------------
// Word abstraction: whole k*k patch bitmap in one "word"
// ---------------------------------------------------------------------------
typedef unsigned int u32;
typedef unsigned long long u64;

struct U128 { u64 lo, hi; };

__device__ __forceinline__ U128 operator|(U128 a, U128 b) { return {a.lo | b.lo, a.hi | b.hi}; }
__device__ __forceinline__ U128 operator&(U128 a, U128 b) { return {a.lo & b.lo, a.hi & b.hi}; }
__device__ __forceinline__ U128 operator~(U128 a) { return {~a.lo, ~a.hi}; }

__device__ __forceinline__ u32  shl(u32 x, int s)  { return x << s; }
__device__ __forceinline__ u32  shr(u32 x, int s)  { return x >> s; }
__device__ __forceinline__ u64  shl(u64 x, int s)  { return x << s; }
__device__ __forceinline__ u64  shr(u64 x, int s)  { return x >> s; }
__device__ __forceinline__ U128 shl(U128 a, int s) {            // 1 <= s <= 63
    return {a.lo << s, (a.hi << s) | (a.lo >> (64 - s))};
}
__device__ __forceinline__ U128 shr(U128 a, int s) {            // 1 <= s <= 63
    return {(a.lo >> s) | (a.hi << (64 - s)), a.hi >> s};
}

__device__ __forceinline__ int popc(u32 x)  { return __popc(x); }
__device__ __forceinline__ int popc(u64 x)  { return __popcll(x); }
__device__ __forceinline__ int popc(U128 a) { return __popcll(a.lo) + __popcll(a.hi); }

__device__ __forceinline__ u32  lsb(u32 x)  { return x & (0u - x); }
__device__ __forceinline__ u64  lsb(u64 x)  { return x & (0ull - x); }
__device__ __forceinline__ U128 lsb(U128 a) {
    if (a.lo) return {a.lo & (0ull - a.lo), 0ull};
    return {0ull, a.hi & (0ull - a.hi)};
}

__device__ __forceinline__ bool any(u32 x)  { return x != 0u; }
__device__ __forceinline__ bool any(u64 x)  { return x != 0ull; }
__device__ __forceinline__ bool any(U128 a) { return (a.lo | a.hi) != 0ull; }

__device__ __forceinline__ bool same(u32 a, u32 b)   { return a == b; }
__device__ __forceinline__ bool same(u64 a, u64 b)   { return a == b; }
__device__ __forceinline__ bool same(U128 a, U128 b) { return a.lo == b.lo && a.hi == b.hi; }

// deposit a K-bit row mask at bit offset s
__device__ __forceinline__ void deposit(u32& w, u32 m, int s, int K)  { w |= m << s; }
__device__ __forceinline__ void deposit(u64& w, u32 m, int s, int K)  { w |= (u64)m << s; }
__device__ __forceinline__ void deposit(U128& w, u32 m, int s, int K) {
    if (s < 64) {
        w.lo |= (u64)m << s;
        int r = 64 - s;
        if (r < K) w.hi |= (u64)m >> r;
    } else {
        w.hi |= (u64)m << (s - 64);
    }
}

// constexpr column-boundary mask: bits b (in [base, base+64)) with b < K*K and
// (b % K) != excl
__host__ __device__ constexpr u64 cmask64(int K, int excl, int base) {
    u64 m = 0;
    for (int b = 0; b < 64; b++) {
        int g = base + b;
        if (g < K * K && (g % K) != excl) m |= (1ull << b);
    }
    return m;
}

template <int K> struct WSel;
template <> struct WSel<3>  { using T = u32; };
template <> struct WSel<5>  { using T = u32; };
template <> struct WSel<7>  { using T = u64; };
template <> struct WSel<9>  { using T = U128; };
template <> struct WSel<11> { using T = U128; };

template <typename W> __device__ __forceinline__ W make_cmask(int K, int excl);
template <> __device__ __forceinline__ u32  make_cmask<u32>(int K, int excl)  {
    return (u32)cmask64(K, excl, 0);
}
template <> __device__ __forceinline__ u64  make_cmask<u64>(int K, int excl)  {
    return cmask64(K, excl, 0);
}
template <> __device__ __forceinline__ U128 make_cmask<U128>(int K, int excl) {
    return {cmask64(K, excl, 0), cmask64(K, excl, 64)};
}

// ---------------------------------------------------------------------------
// Pass 1: NHWC -> planar, float4-vectorized (4 pixels / thread)
// ---------------------------------------------------------------------------
__global__ void transpose_kernel(const float* __restrict__ in) {
    int g = blockIdx.x * blockDim.x + threadIdx.x;   // group of 4 pixels
    if (g >= NPIX / 4) return;
    const float4* p = (const float4*)(in + (size_t)g * 12);
    float4 A = __ldg(&p[0]);   // p0.r p0.g p0.b p1.r
    float4 B = __ldg(&p[1]);   // p1.g p1.b p2.r p2.g
    float4 C = __ldg(&p[2]);   // p2.b p3.r p3.g p3.b
    float4 rch = make_float4(A.x, A.w, B.z, C.y);
    float4 gch = make_float4(A.y, B.x, B.w, C.z);
    float4 bch = make_float4(A.z, B.y, C.x, C.w);
    ((float4*)(g_planar + 0ULL * NPIX))[g] = rch;
    ((float4*)(g_planar + 1ULL * NPIX))[g] = gch;
    ((float4*)(g_planar + 2ULL * NPIX))[g] = bch;
}

// ---------------------------------------------------------------------------
// Pass 2: per-(b, ch, k) block. Patch bitmap packed into one word; strip of
// singletons/dominoes and flood-fill of residual clusters in full-word ops.
// ---------------------------------------------------------------------------
template <int K>
__device__ __forceinline__ void compute_block(int b, int ch, int kidx) {
    constexpr int ROWS = (HW + K - 1) / K;
    constexpr int P = ROWS * ROWS;
    constexpr int PAD = (ROWS * K - HW) / 2;   // top/left pad (== ph // 2)
    constexpr int KK = K * K;
    constexpr u32 RMASK = (1u << K) - 1u;
    using W = typename WSel<K>::T;

    const W CMW = make_cmask<W>(K, 0);       // valid after <<1 (col != 0)
    const W CME = make_cmask<W>(K, K - 1);   // valid after >>1 (col != K-1)

    __shared__ int s_hist[KK + 1];
    __shared__ int s_ncomp, s_perc, s_marea;

    for (int i = threadIdx.x; i < KK + 1; i += blockDim.x) s_hist[i] = 0;
    if (threadIdx.x == 0) { s_ncomp = 0; s_perc = 0; s_marea = 0; }
    __syncthreads();

    const float* img = g_planar + ((size_t)ch * BATCH + b) * IMG_PIX;
    const float thr = (float)K;

    int t_ncomp = 0, t_perc = 0, t_marea = 0;

    for (int p = threadIdx.x; p < P; p += blockDim.x) {
        int pr = p / ROWS, pc = p - pr * ROWS;
        int r0 = pr * K - PAD, c0 = pc * K - PAD;

        // center pixel is always in-bounds for these (K, 224) combos
        float cv = __ldg(&img[(r0 + K / 2) * HW + (c0 + K / 2)]);

        // ---- binarize patch into one packed word ----
        W x = {};
        bool colfast = (c0 >= 0) && (c0 + K <= HW);
        #pragma unroll
        for (int rr = 0; rr < K; rr++) {
            int r = r0 + rr;
            u32 m = 0;
            if (r >= 0 && r < HW) {
                if (colfast) {
                    const float* rp = img + r * HW + c0;
                    #pragma unroll
                    for (int cc = 0; cc < K; cc++) {
                        float v = __ldg(&rp[cc]);
                        m |= (fabsf(v - cv) <= thr) ? (1u << cc) : 0u;
                    }
                } else {
                    #pragma unroll
                    for (int cc = 0; cc < K; cc++) {
                        int c = c0 + cc;
                        float v = (c >= 0 && c < HW) ? __ldg(&img[r * HW + c]) : 0.0f;
                        m |= (fabsf(v - cv) <= thr) ? (1u << cc) : 0u;
                    }
                }
            } else {
                m = (cv <= thr) ? RMASK : 0u;   // fully-padded row (values 0)
            }
            deposit(x, m, rr * K, K);
        }
        int ones = popc(x);

        // ---- bulk strip of singletons and isolated dominoes (full-word) ----
        W Wn = shl(x, 1) & CMW;      // west neighbor present
        W En = shr(x, 1) & CME;      // east
        W Nn = shl(x, K);            // north
        W Sn = shr(x, K);            // south

        W s1 = (Wn | En) & ~(Wn & En);       // XOR via or/andnot (works for U128)
        W c1 = Wn & En;
        W s2 = (Nn | Sn) & ~(Nn & Sn);
        W c2 = Nn & Sn;
        W low = (s1 | s2) & ~(s1 & s2);      // exactly-one of (s1, s2)
        W ge2 = c1 | c2 | (s1 & s2);
        W anyn = low | ge2;

        int n_iso = popc(x & ~anyn);
        W rm = x & anyn;
        W e1 = x & low & ~ge2;               // exactly one neighbor

        W hd = e1 & shr(e1, 1) & CME;        // isolated horizontal dominoes
        int n_dom = popc(hd);
        rm = rm & ~(hd | shl(hd, 1));

        W vd = e1 & shr(e1, K);              // isolated vertical dominoes
        n_dom += popc(vd);
        rm = rm & ~(vd | shl(vd, K));

        int remaining = ones - n_iso - 2 * n_dom;
        int ncomp = n_iso + n_dom;
        int maxc = (n_dom > 0) ? 2 : ((n_iso > 0) ? 1 : 0);

        // ---- flood-fill residual clusters: whole-patch dilate per step ----
        while (remaining > 0) {
            W comp = lsb(rm);
            for (;;) {
                W grow = (comp | (shl(comp, 1) & CMW) | (shr(comp, 1) & CME)
                               | shl(comp, K) | shr(comp, K)) & rm;
                if (same(grow, comp)) break;
                comp = grow;
            }
            int sz = popc(comp);
            rm = rm & ~comp;
            remaining -= sz;
            ncomp++;
            if (sz > maxc) maxc = sz;
        }

        int zeros = KK - ones;
        int marea = (zeros > maxc) ? zeros : maxc;   // label-0 (bg) count vs max comp
        int perc = ((float)ones / (float)KK >= 0.59275f) ? 1 : 0;

        atomicAdd(&s_hist[ones], 1);
        t_ncomp += ncomp;
        t_perc += perc;
        t_marea += marea;
    }

    // warp-reduce the three scalar sums, then one shared atomic per warp
    #pragma unroll
    for (int off = 16; off > 0; off >>= 1) {
        t_ncomp += __shfl_down_sync(0xffffffffu, t_ncomp, off);
        t_perc  += __shfl_down_sync(0xffffffffu, t_perc, off);
        t_marea += __shfl_down_sync(0xffffffffu, t_marea, off);
    }
    if ((threadIdx.x & 31) == 0) {
        atomicAdd(&s_ncomp, t_ncomp);
        atomicAdd(&s_perc, t_perc);
        atomicAdd(&s_marea, t_marea);
    }
    __syncthreads();

    if (threadIdx.x == 0) {
        const float Pf = (float)P;
        float fd = 0.f, m = 0.f, m2 = 0.f;
        for (int j = 0; j < KK; j++) {            // bin KK intentionally dropped
            float pr = (float)s_hist[j] / Pf;
            float n = (float)(j + 1);
            fd += pr / n;
            m  += pr * n;
            m2 += pr * pr * n;
        }
        float lac = (m2 - m * m) / (m * m);
        float acn  = (float)(s_ncomp / P);        // tf integer reduce_mean
        float acp  = (float)(s_perc  / P);
        float acma = (float)(s_marea / P);

        float* g = g_grid + (size_t)b * 75;       // [metric][kidx][ch]
        g[(0 * 5 + kidx) * 3 + ch] = acn;
        g[(1 * 5 + kidx) * 3 + ch] = acp;
        g[(2 * 5 + kidx) * 3 + ch] = acma;
        g[(3 * 5 + kidx) * 3 + ch] = lac;
        g[(4 * 5 + kidx) * 3 + ch] = fd;
    }
}

__global__ __launch_bounds__(256) void compute_kernel() {
    int bid = blockIdx.x;
    int kidx = bid / (BATCH * 3);
    int rest = bid - kidx * (BATCH * 3);
    int b = rest / 3, ch = rest - (rest / 3) * 3;
    switch (kidx) {
        case 0: compute_block<3>(b, ch, 0); break;
        case 1: compute_block<5>(b, ch, 1); break;
        case 2: compute_block<7>(b, ch, 2); break;
        case 3: compute_block<9>(b, ch, 3); break;
        case 4: compute_block<11>(b, ch, 4); break;
    }
}

// ---------------------------------------------------------------------------
// Pass 3: bilinear upsample 5x5x3 -> 224x224x3, float4-vectorized stores
// (half-pixel centers + edge clamp == jax.image.resize 'bilinear' upsampling)
// ---------------------------------------------------------------------------
__global__ void resize_kernel(float* __restrict__ out) {
    int g = blockIdx.x * blockDim.x + threadIdx.x;   // group of 4 pixels
    if (g >= NPIX / 4) return;
    int b = g / (IMG_PIX / 4);
    int within = g - b * (IMG_PIX / 4);
    int pix0 = within * 4;
    int i = pix0 / HW, j0 = pix0 - (pix0 / HW) * HW;  // 4 pixels share row i

    const float scale = 5.0f / 224.0f;
    float fy = ((float)i + 0.5f) * scale - 0.5f;
    float y0f = floorf(fy);
    float wy = fy - y0f;
    int y0 = min(4, max(0, (int)y0f));
    int y1 = min(4, max(0, (int)y0f + 1));

    const float* gr = g_grid + (size_t)b * 75;
    float vals[12];
    #pragma unroll
    for (int q = 0; q < 4; q++) {
        int j = j0 + q;
        float fx = ((float)j + 0.5f) * scale - 0.5f;
        float x0f = floorf(fx);
        float wx = fx - x0f;
        int x0 = min(4, max(0, (int)x0f));
        int x1 = min(4, max(0, (int)x0f + 1));
        #pragma unroll
        for (int c = 0; c < 3; c++) {
            float v00 = __ldg(&gr[(y0 * 5 + x0) * 3 + c]);
            float v01 = __ldg(&gr[(y0 * 5 + x1) * 3 + c]);
            float v10 = __ldg(&gr[(y1 * 5 + x0) * 3 + c]);
            float v11 = __ldg(&gr[(y1 * 5 + x1) * 3 + c]);
            float top = v00 * (1.0f - wx) + v01 * wx;
            float bot = v10 * (1.0f - wx) + v11 * wx;
            vals[q * 3 + c] = top * (1.0f - wy) + bot * wy;
        }
    }
    float4* o = (float4*)(out + (size_t)(b * IMG_PIX + pix0) * 3);
    o[0] = make_float4(vals[0], vals[1], vals[2],  vals[3]);
    o[1] = make_float4(vals[4], vals[5], vals[6],  vals[7]);
    o[2] = make_float4(vals[8], vals[9], vals[10], vals[11]);
}

// ---------------------------------------------------------------------------
extern "C" void kernel_launch(void* const* d_in, const int* in_sizes, int n_in,
                              void* d_out, int out_size) {
    const float* in = (const float*)d_in[0];
    float* out = (float*)d_out;

    transpose_kernel<<<(NPIX / 4 + 255) / 256, 256>>>(in);
    compute_kernel<<<5 * BATCH * 3, 256>>>();
    resize_kernel<<<(NPIX / 4 + 255) / 256, 256>>>(out);
}

// round 9
// speedup vs baseline: 1.8998x; 1.1202x over previous
#include <cuda_runtime.h>
#include <math.h>

#define BATCH 64
#define HW 224
#define IMG_PIX (HW * HW)   // 50176
#define NPIX (BATCH * IMG_PIX)

// Planar scratch with front/rear pad so aligned vector over-fetch never leaves
// the array (front: a0 can be -4; rear: a0+16 can pass the last row end).
__device__ __align__(16) float g_planar_raw[8 + 3ULL * NPIX + 16];
__device__ float g_grid[BATCH * 5 * 5 * 3];  // [b][metric][kidx][ch]

// ---------------------------------------------------------------------------
// Word abstraction: whole k*k patch bitmap in one "word"
// ---------------------------------------------------------------------------
typedef unsigned int u32;
typedef unsigned long long u64;

struct U128 { u64 lo, hi; };

__device__ __forceinline__ U128 operator|(U128 a, U128 b) { return {a.lo | b.lo, a.hi | b.hi}; }
__device__ __forceinline__ U128 operator&(U128 a, U128 b) { return {a.lo & b.lo, a.hi & b.hi}; }
__device__ __forceinline__ U128 operator~(U128 a) { return {~a.lo, ~a.hi}; }

__device__ __forceinline__ u32  shl(u32 x, int s)  { return x << s; }
__device__ __forceinline__ u32  shr(u32 x, int s)  { return x >> s; }
__device__ __forceinline__ u64  shl(u64 x, int s)  { return x << s; }
__device__ __forceinline__ u64  shr(u64 x, int s)  { return x >> s; }
__device__ __forceinline__ U128 shl(U128 a, int s) {            // 1 <= s <= 63
    return {a.lo << s, (a.hi << s) | (a.lo >> (64 - s))};
}
__device__ __forceinline__ U128 shr(U128 a, int s) {            // 1 <= s <= 63
    return {(a.lo >> s) | (a.hi << (64 - s)), a.hi >> s};
}

__device__ __forceinline__ int popc(u32 x)  { return __popc(x); }
__device__ __forceinline__ int popc(u64 x)  { return __popcll(x); }
__device__ __forceinline__ int popc(U128 a) { return __popcll(a.lo) + __popcll(a.hi); }

__device__ __forceinline__ u32  lsb(u32 x)  { return x & (0u - x); }
__device__ __forceinline__ u64  lsb(u64 x)  { return x & (0ull - x); }
__device__ __forceinline__ U128 lsb(U128 a) {
    if (a.lo) return {a.lo & (0ull - a.lo), 0ull};
    return {0ull, a.hi & (0ull - a.hi)};
}

__device__ __forceinline__ bool same(u32 a, u32 b)   { return a == b; }
__device__ __forceinline__ bool same(u64 a, u64 b)   { return a == b; }
__device__ __forceinline__ bool same(U128 a, U128 b) { return a.lo == b.lo && a.hi == b.hi; }

// deposit a K-bit row mask at bit offset s
__device__ __forceinline__ void deposit(u32& w, u32 m, int s, int K)  { w |= m << s; }
__device__ __forceinline__ void deposit(u64& w, u32 m, int s, int K)  { w |= (u64)m << s; }
__device__ __forceinline__ void deposit(U128& w, u32 m, int s, int K) {
    if (s < 64) {
        w.lo |= (u64)m << s;
        int r = 64 - s;
        if (r < K) w.hi |= (u64)m >> r;
    } else {
        w.hi |= (u64)m << (s - 64);
    }
}

// constexpr column-boundary mask: bits b (in [base, base+64)) with b < K*K and
// (b % K) != excl
__host__ __device__ constexpr u64 cmask64(int K, int excl, int base) {
    u64 m = 0;
    for (int b = 0; b < 64; b++) {
        int g = base + b;
        if (g < K * K && (g % K) != excl) m |= (1ull << b);
    }
    return m;
}

template <int K> struct WSel;
template <> struct WSel<3>  { using T = u32; };
template <> struct WSel<5>  { using T = u32; };
template <> struct WSel<7>  { using T = u64; };
template <> struct WSel<9>  { using T = U128; };
template <> struct WSel<11> { using T = U128; };

template <typename W> __device__ __forceinline__ W make_cmask(int K, int excl);
template <> __device__ __forceinline__ u32  make_cmask<u32>(int K, int excl)  {
    return (u32)cmask64(K, excl, 0);
}
template <> __device__ __forceinline__ u64  make_cmask<u64>(int K, int excl)  {
    return cmask64(K, excl, 0);
}
template <> __device__ __forceinline__ U128 make_cmask<U128>(int K, int excl) {
    return {cmask64(K, excl, 0), cmask64(K, excl, 64)};
}

// ---------------------------------------------------------------------------
// Pass 1: NHWC -> planar, float4-vectorized (4 pixels / thread)
// ---------------------------------------------------------------------------
__global__ void transpose_kernel(const float* __restrict__ in) {
    int g = blockIdx.x * blockDim.x + threadIdx.x;   // group of 4 pixels
    if (g >= NPIX / 4) return;
    float* planar = g_planar_raw + 8;
    const float4* p = (const float4*)(in + (size_t)g * 12);
    float4 A = __ldg(&p[0]);   // p0.r p0.g p0.b p1.r
    float4 B = __ldg(&p[1]);   // p1.g p1.b p2.r p2.g
    float4 C = __ldg(&p[2]);   // p2.b p3.r p3.g p3.b
    float4 rch = make_float4(A.x, A.w, B.z, C.y);
    float4 gch = make_float4(A.y, B.x, B.w, C.z);
    float4 bch = make_float4(A.z, B.y, C.x, C.w);
    ((float4*)(planar + 0ULL * NPIX))[g] = rch;
    ((float4*)(planar + 1ULL * NPIX))[g] = gch;
    ((float4*)(planar + 2ULL * NPIX))[g] = bch;
}

// ---------------------------------------------------------------------------
// Pass 2: per-(b, ch, k) block. Branch-free vectorized binarize (aligned
// LDG.128 over-fetch + mask extraction), word-packed strip + flood.
// ---------------------------------------------------------------------------
template <int K>
__device__ __forceinline__ void compute_block(int b, int ch, int kidx) {
    constexpr int ROWS = (HW + K - 1) / K;
    constexpr int P = ROWS * ROWS;
    constexpr int PAD = (ROWS * K - HW) / 2;   // top/left pad (== ph // 2)
    constexpr int KK = K * K;
    constexpr u32 RMASK = (1u << K) - 1u;
    constexpr int W4 = (K + 3 + 3) / 4;        // float4 loads per row (off<=3)
    using W = typename WSel<K>::T;

    const W CMW = make_cmask<W>(K, 0);       // valid after <<1 (col != 0)
    const W CME = make_cmask<W>(K, K - 1);   // valid after >>1 (col != K-1)

    __shared__ int s_hist[KK + 1];
    __shared__ int s_ncomp, s_perc, s_marea;

    for (int i = threadIdx.x; i < KK + 1; i += blockDim.x) s_hist[i] = 0;
    if (threadIdx.x == 0) { s_ncomp = 0; s_perc = 0; s_marea = 0; }
    __syncthreads();

    const float* img = g_planar_raw + 8 + ((size_t)ch * BATCH + b) * IMG_PIX;
    const float thr = (float)K;

    int t_ncomp = 0, t_perc = 0, t_marea = 0;
    const int lane = threadIdx.x & 31;

    // uniform trip count so full-warp __match_any_sync is legal
    for (int p0 = 0; p0 < P; p0 += blockDim.x) {
        int pidx = p0 + threadIdx.x;
        bool valid = pidx < P;
        int p = valid ? pidx : 0;

        int pr = p / ROWS, pc = p - pr * ROWS;
        int r0 = pr * K - PAD, c0 = pc * K - PAD;

        // center pixel is always in-bounds for these (K, 224) combos
        float cv = __ldg(&img[(r0 + K / 2) * HW + (c0 + K / 2)]);
        u32 padrow = (cv <= thr) ? RMASK : 0u;   // value of a fully-padded row

        // per-patch column validity mask (branch-free edge handling)
        int lo = (c0 < 0) ? -c0 : 0;                       // <= 3
        int hi = (c0 + K > HW) ? (HW - c0) : K;            // in [1, K]
        u32 vmask = ((1u << hi) - 1u) & ~((1u << lo) - 1u);
        u32 padbits = padrow & ~vmask;                     // zero-pad columns

        int a0 = c0 & ~3;            // aligned float4 base (rounds down for <0)
        int off = c0 - a0;           // 0..3

        // ---- binarize patch into one packed word ----
        W x = {};
        #pragma unroll
        for (int rr = 0; rr < K; rr++) {
            int r = r0 + rr;
            u32 m;
            if (r >= 0 && r < HW) {
                const float4* rp4 = (const float4*)(img + r * HW + a0);
                u32 m16 = 0;
                #pragma unroll
                for (int w = 0; w < W4; w++) {
                    float4 q = __ldg(&rp4[w]);
                    m16 |= (fabsf(q.x - cv) <= thr) ? (1u << (4 * w + 0)) : 0u;
                    m16 |= (fabsf(q.y - cv) <= thr) ? (1u << (4 * w + 1)) : 0u;
                    m16 |= (fabsf(q.z - cv) <= thr) ? (1u << (4 * w + 2)) : 0u;
                    m16 |= (fabsf(q.w - cv) <= thr) ? (1u << (4 * w + 3)) : 0u;
                }
                m = ((m16 >> off) & vmask) | padbits;
            } else {
                m = padrow;   // fully-padded row (values 0)
            }
            deposit(x, m, rr * K, K);
        }
        int ones = popc(x);

        // ---- bulk strip of singletons and isolated dominoes (full-word) ----
        W Wn = shl(x, 1) & CMW;      // west neighbor present
        W En = shr(x, 1) & CME;      // east
        W Nn = shl(x, K);            // north
        W Sn = shr(x, K);            // south

        W s1 = (Wn | En) & ~(Wn & En);
        W c1 = Wn & En;
        W s2 = (Nn | Sn) & ~(Nn & Sn);
        W c2 = Nn & Sn;
        W low = (s1 | s2) & ~(s1 & s2);
        W ge2 = c1 | c2 | (s1 & s2);
        W anyn = low | ge2;

        int n_iso = popc(x & ~anyn);
        W rm = x & anyn;
        W e1 = x & low & ~ge2;               // exactly one neighbor

        W hd = e1 & shr(e1, 1) & CME;        // isolated horizontal dominoes
        int n_dom = popc(hd);
        rm = rm & ~(hd | shl(hd, 1));

        W vd = e1 & shr(e1, K);              // isolated vertical dominoes
        n_dom += popc(vd);
        rm = rm & ~(vd | shl(vd, K));

        int remaining = ones - n_iso - 2 * n_dom;
        int ncomp = n_iso + n_dom;
        int maxc = (n_dom > 0) ? 2 : ((n_iso > 0) ? 1 : 0);

        // ---- flood-fill residual clusters: whole-patch dilate per step ----
        while (remaining > 0) {
            W comp = lsb(rm);
            for (;;) {
                W grow = (comp | (shl(comp, 1) & CMW) | (shr(comp, 1) & CME)
                               | shl(comp, K) | shr(comp, K)) & rm;
                if (same(grow, comp)) break;
                comp = grow;
            }
            int sz = popc(comp);
            rm = rm & ~comp;
            remaining -= sz;
            ncomp++;
            if (sz > maxc) maxc = sz;
        }

        int zeros = KK - ones;
        int marea = (zeros > maxc) ? zeros : maxc;
        int perc = ((float)ones / (float)KK >= 0.59275f) ? 1 : 0;

        // histogram: one atomic per distinct 'ones' value per warp
        int key = valid ? ones : 0x7FFFFFFF;
        u32 grp = __match_any_sync(0xffffffffu, key);
        if (valid && lane == (__ffs(grp) - 1))
            atomicAdd(&s_hist[ones], __popc(grp));

        if (valid) {
            t_ncomp += ncomp;
            t_perc += perc;
            t_marea += marea;
        }
    }

    // warp-reduce the three scalar sums, then one shared atomic per warp
    #pragma unroll
    for (int off = 16; off > 0; off >>= 1) {
        t_ncomp += __shfl_down_sync(0xffffffffu, t_ncomp, off);
        t_perc  += __shfl_down_sync(0xffffffffu, t_perc, off);
        t_marea += __shfl_down_sync(0xffffffffu, t_marea, off);
    }
    if (lane == 0) {
        atomicAdd(&s_ncomp, t_ncomp);
        atomicAdd(&s_perc, t_perc);
        atomicAdd(&s_marea, t_marea);
    }
    __syncthreads();

    if (threadIdx.x == 0) {
        const float Pf = (float)P;
        float fd = 0.f, m = 0.f, m2 = 0.f;
        for (int j = 0; j < KK; j++) {            // bin KK intentionally dropped
            float pr = (float)s_hist[j] / Pf;
            float n = (float)(j + 1);
            fd += pr / n;
            m  += pr * n;
            m2 += pr * pr * n;
        }
        float lac = (m2 - m * m) / (m * m);
        float acn  = (float)(s_ncomp / P);        // tf integer reduce_mean
        float acp  = (float)(s_perc  / P);
        float acma = (float)(s_marea / P);

        float* g = g_grid + (size_t)b * 75;       // [metric][kidx][ch]
        g[(0 * 5 + kidx) * 3 + ch] = acn;
        g[(1 * 5 + kidx) * 3 + ch] = acp;
        g[(2 * 5 + kidx) * 3 + ch] = acma;
        g[(3 * 5 + kidx) * 3 + ch] = lac;
        g[(4 * 5 + kidx) * 3 + ch] = fd;
    }
}

__global__ __launch_bounds__(256) void compute_kernel() {
    int bid = blockIdx.x;
    int kidx = bid / (BATCH * 3);
    int rest = bid - kidx * (BATCH * 3);
    int b = rest / 3, ch = rest - (rest / 3) * 3;
    switch (kidx) {
        case 0: compute_block<3>(b, ch, 0); break;
        case 1: compute_block<5>(b, ch, 1); break;
        case 2: compute_block<7>(b, ch, 2); break;
        case 3: compute_block<9>(b, ch, 3); break;
        case 4: compute_block<11>(b, ch, 4); break;
    }
}

// ---------------------------------------------------------------------------
// Pass 3: bilinear upsample 5x5x3 -> 224x224x3, float4-vectorized stores
// (half-pixel centers + edge clamp == jax.image.resize 'bilinear' upsampling)
// ---------------------------------------------------------------------------
__global__ void resize_kernel(float* __restrict__ out) {
    int g = blockIdx.x * blockDim.x + threadIdx.x;   // group of 4 pixels
    if (g >= NPIX / 4) return;
    int b = g / (IMG_PIX / 4);
    int within = g - b * (IMG_PIX / 4);
    int pix0 = within * 4;
    int i = pix0 / HW, j0 = pix0 - (pix0 / HW) * HW;  // 4 pixels share row i

    const float scale = 5.0f / 224.0f;
    float fy = ((float)i + 0.5f) * scale - 0.5f;
    float y0f = floorf(fy);
    float wy = fy - y0f;
    int y0 = min(4, max(0, (int)y0f));
    int y1 = min(4, max(0, (int)y0f + 1));

    const float* gr = g_grid + (size_t)b * 75;
    float vals[12];
    #pragma unroll
    for (int q = 0; q < 4; q++) {
        int j = j0 + q;
        float fx = ((float)j + 0.5f) * scale - 0.5f;
        float x0f = floorf(fx);
        float wx = fx - x0f;
        int x0 = min(4, max(0, (int)x0f));
        int x1 = min(4, max(0, (int)x0f + 1));
        #pragma unroll
        for (int c = 0; c < 3; c++) {
            float v00 = __ldg(&gr[(y0 * 5 + x0) * 3 + c]);
            float v01 = __ldg(&gr[(y0 * 5 + x1) * 3 + c]);
            float v10 = __ldg(&gr[(y1 * 5 + x0) * 3 + c]);
            float v11 = __ldg(&gr[(y1 * 5 + x1) * 3 + c]);
            float top = v00 * (1.0f - wx) + v01 * wx;
            float bot = v10 * (1.0f - wx) + v11 * wx;
            vals[q * 3 + c] = top * (1.0f - wy) + bot * wy;
        }
    }
    float4* o = (float4*)(out + (size_t)(b * IMG_PIX + pix0) * 3);
    o[0] = make_float4(vals[0], vals[1], vals[2],  vals[3]);
    o[1] = make_float4(vals[4], vals[5], vals[6],  vals[7]);
    o[2] = make_float4(vals[8], vals[9], vals[10], vals[11]);
}

// ---------------------------------------------------------------------------
extern "C" void kernel_launch(void* const* d_in, const int* in_sizes, int n_in,
                              void* d_out, int out_size) {
    const float* in = (const float*)d_in[0];
    float* out = (float*)d_out;

    transpose_kernel<<<(NPIX / 4 + 255) / 256, 256>>>(in);
    compute_kernel<<<5 * BATCH * 3, 256>>>();
    resize_kernel<<<(NPIX / 4 + 255) / 256, 256>>>(out);
}